// round 3
// baseline (speedup 1.0000x reference)
#include <cuda_runtime.h>
#include <cuda_bf16.h>

#define NN 100000
#define EE 1600000
#define K_DIM 128
#define BN_EPS 1e-5f

// ---------------- scratch (static device globals; no allocation) ----------------
__device__ float g_h[(size_t)NN * 128];     // GEMM output (used 64-wide for layer3)
__device__ float g_a[(size_t)NN * 128];     // aggregation output
__device__ float g_degw[NN];
__device__ float g_dinv[NN];
__device__ int   g_counts[NN];
__device__ int   g_rowptr[NN + 1];
__device__ int   g_cursor[NN];
__device__ int   g_col[EE];
__device__ float g_val[EE];
__device__ float g_sum[128];
__device__ float g_ssq[128];
__device__ float g_scale[128];
__device__ float g_shift[128];
__device__ int   g_is64;

// edge index fetch honoring detected dtype
__device__ __forceinline__ int edge_at(const void* ei, size_t idx) {
    if (g_is64) return (int)((const long long*)ei)[idx];
    return ((const int*)ei)[idx];
}

// ---------------- dtype detection (deterministic, device-side) ----------------
__global__ void k_detect(const int* __restrict__ ei_words) {
    // int64 data with values < 2^31 has every odd 32-bit word == 0.
    bool is64 = true;
    for (int i = 0; i < 128; i++)
        if (ei_words[2 * i + 1] != 0) { is64 = false; break; }
    g_is64 = is64 ? 1 : 0;
}

// ---------------- graph preprocessing ----------------
__global__ void k_init() {
    int i = blockIdx.x * blockDim.x + threadIdx.x;
    if (i < NN) { g_degw[i] = 1.0f; g_counts[i] = 0; }   // self-loop weight 1
}

__global__ void k_degcount(const void* __restrict__ ei, const float* __restrict__ ew) {
    int e = blockIdx.x * blockDim.x + threadIdx.x;
    if (e < EE) {
        int d = edge_at(ei, (size_t)EE + e);
        if ((unsigned)d < NN) {
            atomicAdd(&g_degw[d], ew[e]);
            atomicAdd(&g_counts[d], 1);
        }
    }
}

__global__ void k_dinv() {
    int i = blockIdx.x * blockDim.x + threadIdx.x;
    if (i < NN) g_dinv[i] = rsqrtf(g_degw[i]);   // degw >= 1 always
}

// single-block exclusive scan of counts -> rowptr (and cursor copy)
__global__ void k_scan() {
    __shared__ int sm[1024];
    int t = threadIdx.x;
    const int chunk = (NN + 1023) / 1024;
    int beg = t * chunk;
    int end = min(beg + chunk, NN);
    int s = 0;
    for (int i = beg; i < end; i++) s += g_counts[i];
    sm[t] = s;
    __syncthreads();
    for (int off = 1; off < 1024; off <<= 1) {
        int v = (t >= off) ? sm[t - off] : 0;
        __syncthreads();
        sm[t] += v;
        __syncthreads();
    }
    int run = (t == 0) ? 0 : sm[t - 1];
    for (int i = beg; i < end; i++) {
        g_rowptr[i] = run; g_cursor[i] = run; run += g_counts[i];
    }
    if (t == 0) g_rowptr[NN] = EE;
}

__global__ void k_fill(const void* __restrict__ ei, const float* __restrict__ ew) {
    int e = blockIdx.x * blockDim.x + threadIdx.x;
    if (e < EE) {
        int s = edge_at(ei, (size_t)e);
        int d = edge_at(ei, (size_t)EE + e);
        if ((unsigned)s >= NN || (unsigned)d >= NN) return;
        float w = ew[e];
        int pos = atomicAdd(&g_cursor[d], 1);
        g_col[pos] = s;
        g_val[pos] = g_dinv[s] * w * g_dinv[d];
    }
}

// ---------------- GEMM: g_h[M x BDN] = act(X) @ W, K = 128 ----------------
// BM=128, Kc=32, 256 threads. Thread tile: 8 x TN. Optional fused BN+ReLU on X load.
// Xin == nullptr -> read from g_a.
template <int BDN, int TN>
__global__ __launch_bounds__(256) void k_gemm(
    const float* __restrict__ Xin, const float* __restrict__ W, int use_bn)
{
    __shared__ float xs[32][132];       // k-major, padded (132*4 = 528 B, 16B-divisible)
    __shared__ float ws[32][BDN];

    const float* X = Xin ? Xin : g_a;

    const int tid = threadIdx.x;
    const int m0 = blockIdx.x * 128;
    const int row0 = (tid >> 4) * 8;
    const int col0 = (tid & 15) * TN;

    float acc[8][TN];
#pragma unroll
    for (int i = 0; i < 8; i++)
#pragma unroll
        for (int j = 0; j < TN; j++) acc[i][j] = 0.0f;

    for (int kc = 0; kc < K_DIM / 32; kc++) {
        // load X tile (128 rows x 32 k) transposed into xs, with optional BN+ReLU
#pragma unroll
        for (int i = 0; i < 4; i++) {
            int fid = tid + i * 256;     // 0..1023
            int row = fid >> 3;
            int kv  = fid & 7;
            int m = m0 + row;
            float4 v = make_float4(0.f, 0.f, 0.f, 0.f);
            if (m < NN) {
                v = *(const float4*)(X + (size_t)m * K_DIM + kc * 32 + kv * 4);
                if (use_bn) {
                    int ch = kc * 32 + kv * 4;
                    v.x = fmaxf(0.f, v.x * g_scale[ch + 0] + g_shift[ch + 0]);
                    v.y = fmaxf(0.f, v.y * g_scale[ch + 1] + g_shift[ch + 1]);
                    v.z = fmaxf(0.f, v.z * g_scale[ch + 2] + g_shift[ch + 2]);
                    v.w = fmaxf(0.f, v.w * g_scale[ch + 3] + g_shift[ch + 3]);
                }
            }
            xs[kv * 4 + 0][row] = v.x;
            xs[kv * 4 + 1][row] = v.y;
            xs[kv * 4 + 2][row] = v.z;
            xs[kv * 4 + 3][row] = v.w;
        }
        // load W tile (32 k x BDN)
#pragma unroll
        for (int i = 0; i < BDN / 32; i++) {
            int fid = tid + i * 256;
            int row = fid / (BDN / 4);
            int c   = fid % (BDN / 4);
            float4 v = *(const float4*)(W + (size_t)(kc * 32 + row) * BDN + c * 4);
            *(float4*)&ws[row][c * 4] = v;
        }
        __syncthreads();

#pragma unroll
        for (int k = 0; k < 32; k++) {
            float a[8], b[TN];
            *(float4*)(a + 0) = *(const float4*)&xs[k][row0];
            *(float4*)(a + 4) = *(const float4*)&xs[k][row0 + 4];
#pragma unroll
            for (int j4 = 0; j4 < TN / 4; j4++)
                *(float4*)(b + j4 * 4) = *(const float4*)&ws[k][col0 + j4 * 4];
#pragma unroll
            for (int i = 0; i < 8; i++)
#pragma unroll
                for (int j = 0; j < TN; j++) acc[i][j] = fmaf(a[i], b[j], acc[i][j]);
        }
        __syncthreads();
    }

#pragma unroll
    for (int i = 0; i < 8; i++) {
        int m = m0 + row0 + i;
        if (m < NN) {
#pragma unroll
            for (int j4 = 0; j4 < TN / 4; j4++) {
                float4 v = make_float4(acc[i][j4 * 4 + 0], acc[i][j4 * 4 + 1],
                                       acc[i][j4 * 4 + 2], acc[i][j4 * 4 + 3]);
                *(float4*)(g_h + (size_t)m * BDN + col0 + j4 * 4) = v;
            }
        }
    }
}

// ---------------- aggregation: out[n] = sum_{e: dst=n} h[src]*norm + h[n]*dinv^2 + bias ----------------
// outp == nullptr -> write to g_a.
template <int D>
__global__ __launch_bounds__(256) void k_agg(
    const float* __restrict__ bias, float* __restrict__ outp)
{
    const int warp = (blockIdx.x * blockDim.x + threadIdx.x) >> 5;
    const int lane = threadIdx.x & 31;
    if (warp >= NN) return;

    const float* H = g_h;
    float* out = outp ? outp : g_a;

    constexpr int VEC = D / 32;   // 4 (D=128) or 2 (D=64)
    float acc[VEC];

    float dn = g_dinv[warp];
    float selfw = dn * dn;
    {
        const float* hp = H + (size_t)warp * D + lane * VEC;
        if (VEC == 4) {
            float4 h4 = *(const float4*)hp;
            acc[0] = h4.x * selfw; acc[1] = h4.y * selfw;
            acc[2] = h4.z * selfw; acc[3] = h4.w * selfw;
        } else {
            float2 h2 = *(const float2*)hp;
            acc[0] = h2.x * selfw; acc[1] = h2.y * selfw;
        }
    }

    int beg = g_rowptr[warp];
    int end = g_rowptr[warp + 1];
    for (int base = beg; base < end; base += 32) {
        int idx = base + lane;
        int c = 0; float v = 0.f;
        if (idx < end) { c = g_col[idx]; v = g_val[idx]; }
        int cnt = min(32, end - base);
        for (int j = 0; j < cnt; j++) {
            int s   = __shfl_sync(0xffffffffu, c, j);
            float w = __shfl_sync(0xffffffffu, v, j);
            const float* hp = H + (size_t)s * D + lane * VEC;
            if (VEC == 4) {
                float4 h4 = *(const float4*)hp;
                acc[0] = fmaf(h4.x, w, acc[0]); acc[1] = fmaf(h4.y, w, acc[1]);
                acc[2] = fmaf(h4.z, w, acc[2]); acc[3] = fmaf(h4.w, w, acc[3]);
            } else {
                float2 h2 = *(const float2*)hp;
                acc[0] = fmaf(h2.x, w, acc[0]); acc[1] = fmaf(h2.y, w, acc[1]);
            }
        }
    }

    float* op = out + (size_t)warp * D + lane * VEC;
    if (VEC == 4) {
        float4 b4 = *(const float4*)(bias + lane * 4);
        *(float4*)op = make_float4(acc[0] + b4.x, acc[1] + b4.y, acc[2] + b4.z, acc[3] + b4.w);
    } else {
        float2 b2 = *(const float2*)(bias + lane * 2);
        *(float2*)op = make_float2(acc[0] + b2.x, acc[1] + b2.y);
    }
}

// ---------------- batch-norm stats (over g_a) ----------------
__global__ void k_zero_stats() {
    int c = threadIdx.x;
    if (c < 128) { g_sum[c] = 0.f; g_ssq[c] = 0.f; }
}

#define STATS_RPB 250
__global__ __launch_bounds__(128) void k_stats() {
    int c = threadIdx.x;
    int r0 = blockIdx.x * STATS_RPB;
    float sum = 0.f, ssq = 0.f;
    int rend = min(r0 + STATS_RPB, NN);
    for (int r = r0; r < rend; r++) {
        float v = g_a[(size_t)r * 128 + c];
        sum += v; ssq += v * v;
    }
    atomicAdd(&g_sum[c], sum);
    atomicAdd(&g_ssq[c], ssq);
}

__global__ void k_bnfin(const float* __restrict__ gamma, const float* __restrict__ beta) {
    int c = threadIdx.x;
    if (c < 128) {
        float mean = g_sum[c] / (float)NN;
        float var  = g_ssq[c] / (float)NN - mean * mean;
        float inv  = rsqrtf(var + BN_EPS);
        float sc   = gamma[c] * inv;
        g_scale[c] = sc;
        g_shift[c] = beta[c] - mean * sc;
    }
}

// ---------------- launch (pure kernel launches; no runtime API) ----------------
extern "C" void kernel_launch(void* const* d_in, const int* in_sizes, int n_in,
                              void* d_out, int out_size) {
    const float* x   = (const float*)d_in[0];
    const void*  ei  = d_in[1];                   // int32 or int64, detected on device
    const float* ew  = (const float*)d_in[2];
    const float* W1  = (const float*)d_in[3];
    const float* b1  = (const float*)d_in[4];
    const float* W2  = (const float*)d_in[5];
    const float* b2  = (const float*)d_in[6];
    const float* W3  = (const float*)d_in[7];
    const float* b3  = (const float*)d_in[8];
    const float* g1  = (const float*)d_in[9];
    const float* be1 = (const float*)d_in[10];
    const float* g2  = (const float*)d_in[11];
    const float* be2 = (const float*)d_in[12];
    float* out = (float*)d_out;

    const int nb_n = (NN + 255) / 256;
    const int nb_e = (EE + 255) / 256;
    const int gemm_blocks = (NN + 127) / 128;
    const int agg_blocks = (NN + 7) / 8;          // 8 warps/block
    const int stats_blocks = (NN + STATS_RPB - 1) / STATS_RPB;

    // --- graph preprocessing ---
    k_detect<<<1, 1>>>((const int*)ei);
    k_init<<<nb_n, 256>>>();
    k_degcount<<<nb_e, 256>>>(ei, ew);
    k_dinv<<<nb_n, 256>>>();
    k_scan<<<1, 1024>>>();
    k_fill<<<nb_e, 256>>>(ei, ew);

    // --- layer 1 ---
    k_gemm<128, 8><<<gemm_blocks, 256>>>(x, W1, 0);
    k_agg<128><<<agg_blocks, 256>>>(b1, nullptr);
    k_zero_stats<<<1, 128>>>();
    k_stats<<<stats_blocks, 128>>>();
    k_bnfin<<<1, 128>>>(g1, be1);

    // --- layer 2 (BN1+ReLU fused into GEMM X-load) ---
    k_gemm<128, 8><<<gemm_blocks, 256>>>(nullptr, W2, 1);
    k_agg<128><<<agg_blocks, 256>>>(b2, nullptr);
    k_zero_stats<<<1, 128>>>();
    k_stats<<<stats_blocks, 128>>>();
    k_bnfin<<<1, 128>>>(g2, be2);

    // --- layer 3 (BN2+ReLU fused; 64-wide output straight to d_out) ---
    k_gemm<64, 4><<<gemm_blocks, 256>>>(nullptr, W3, 1);
    k_agg<64><<<agg_blocks, 256>>>(b3, out);
}

// round 4
// speedup vs baseline: 1.2413x; 1.2413x over previous
#include <cuda_runtime.h>
#include <cuda_bf16.h>

#define NN 100000
#define EE 1600000
#define K_DIM 128
#define BN_EPS 1e-5f

// ---------------- scratch (static device globals; no allocation) ----------------
__device__ float g_h[(size_t)NN * 128];     // GEMM output (used 64-wide for layer3)
__device__ float g_a[(size_t)NN * 128];     // aggregation output
__device__ float g_degw[NN];
__device__ float g_dinv[NN];
__device__ int   g_counts[NN];
__device__ int   g_rowptr[NN + 1];
__device__ int   g_cursor[NN];
__device__ int   g_col[EE];
__device__ float g_val[EE];
__device__ float g_sum[128];
__device__ float g_ssq[128];
__device__ float g_scale[128];
__device__ float g_shift[128];
__device__ int   g_is64;

// edge index fetch honoring detected dtype
__device__ __forceinline__ int edge_at(const void* ei, size_t idx) {
    if (g_is64) return (int)((const long long*)ei)[idx];
    return ((const int*)ei)[idx];
}

// ---------------- dtype detection (deterministic, device-side) ----------------
__global__ void k_detect(const int* __restrict__ ei_words) {
    // int64 data with values < 2^31 has every odd 32-bit word == 0.
    bool is64 = true;
    for (int i = 0; i < 128; i++)
        if (ei_words[2 * i + 1] != 0) { is64 = false; break; }
    g_is64 = is64 ? 1 : 0;
}

// ---------------- graph preprocessing ----------------
__global__ void k_init() {
    int i = blockIdx.x * blockDim.x + threadIdx.x;
    if (i < NN) { g_degw[i] = 1.0f; g_counts[i] = 0; }   // self-loop weight 1
}

__global__ void k_degcount(const void* __restrict__ ei, const float* __restrict__ ew) {
    int e = blockIdx.x * blockDim.x + threadIdx.x;
    if (e < EE) {
        int d = edge_at(ei, (size_t)EE + e);
        if ((unsigned)d < NN) {
            atomicAdd(&g_degw[d], ew[e]);
            atomicAdd(&g_counts[d], 1);
        }
    }
}

__global__ void k_dinv() {
    int i = blockIdx.x * blockDim.x + threadIdx.x;
    if (i < NN) g_dinv[i] = rsqrtf(g_degw[i]);   // degw >= 1 always
}

// single-block exclusive scan of counts -> rowptr (and cursor copy)
__global__ void k_scan() {
    __shared__ int sm[1024];
    int t = threadIdx.x;
    const int chunk = (NN + 1023) / 1024;
    int beg = t * chunk;
    int end = min(beg + chunk, NN);
    int s = 0;
    for (int i = beg; i < end; i++) s += g_counts[i];
    sm[t] = s;
    __syncthreads();
    for (int off = 1; off < 1024; off <<= 1) {
        int v = (t >= off) ? sm[t - off] : 0;
        __syncthreads();
        sm[t] += v;
        __syncthreads();
    }
    int run = (t == 0) ? 0 : sm[t - 1];
    for (int i = beg; i < end; i++) {
        g_rowptr[i] = run; g_cursor[i] = run; run += g_counts[i];
    }
    if (t == 0) g_rowptr[NN] = EE;
}

__global__ void k_fill(const void* __restrict__ ei, const float* __restrict__ ew) {
    int e = blockIdx.x * blockDim.x + threadIdx.x;
    if (e < EE) {
        int s = edge_at(ei, (size_t)e);
        int d = edge_at(ei, (size_t)EE + e);
        if ((unsigned)s >= NN || (unsigned)d >= NN) return;
        float w = ew[e];
        int pos = atomicAdd(&g_cursor[d], 1);
        g_col[pos] = s;
        g_val[pos] = g_dinv[s] * w * g_dinv[d];
    }
}

// ---------------- tf32 helpers ----------------
__device__ __forceinline__ float to_tf32(float x) {
    unsigned u;
    asm("cvt.rna.tf32.f32 %0, %1;" : "=r"(u) : "f"(x));
    return __uint_as_float(u);
}

__device__ __forceinline__ void mma_tf32(
    float& d0, float& d1, float& d2, float& d3,
    float a0, float a1, float a2, float a3,
    float b0, float b1)
{
    asm volatile(
        "mma.sync.aligned.m16n8k8.row.col.f32.tf32.tf32.f32 "
        "{%0,%1,%2,%3}, {%4,%5,%6,%7}, {%8,%9}, {%0,%1,%2,%3};"
        : "+f"(d0), "+f"(d1), "+f"(d2), "+f"(d3)
        : "r"(__float_as_uint(a0)), "r"(__float_as_uint(a1)),
          "r"(__float_as_uint(a2)), "r"(__float_as_uint(a3)),
          "r"(__float_as_uint(b0)), "r"(__float_as_uint(b1)));
}

// ---------------- GEMM (tf32 tensor cores): g_h[NN x BN] = act(X) @ W ----------------
// Block tile 128 x BN, 8 warps (2 x 4), warp tile 64 x (BN/4). K chunked by 32.
// Optional fused BN+ReLU on X load. Xin == nullptr -> read from g_a.
template <int BN>
__global__ __launch_bounds__(256) void k_gemm_tc(
    const float* __restrict__ Xin, const float* __restrict__ W, int use_bn)
{
    constexpr int WN = BN / 4;        // 32 or 16
    constexpr int NT = WN / 8;        // n-tiles per warp: 4 or 2
    constexpr int XP = 36;            // xs row stride (conflict-free A-frag reads)
    constexpr int WP = BN + 8;        // ws row stride (conflict-free B-frag reads)

    __shared__ float xs[128 * XP];    // [m][k]
    __shared__ float ws[32 * WP];     // [k][n]

    const float* X = Xin ? Xin : g_a;

    const int tid = threadIdx.x;
    const int wid = tid >> 5, lane = tid & 31;
    const int gid = lane >> 2, tig = lane & 3;   // groupID, thread-in-group
    const int warpM = wid >> 2, warpN = wid & 3; // 2 x 4 warp grid
    const int m0 = blockIdx.x * 128;

    float acc[4][NT][4];
#pragma unroll
    for (int mt = 0; mt < 4; mt++)
#pragma unroll
        for (int nt = 0; nt < NT; nt++)
#pragma unroll
            for (int r = 0; r < 4; r++) acc[mt][nt][r] = 0.0f;

    for (int kc = 0; kc < 4; kc++) {
        // X chunk: 128 rows x 32 k  (1024 float4 slots, 4 per thread)
#pragma unroll
        for (int i = 0; i < 4; i++) {
            int fid = tid + i * 256;
            int row = fid >> 3;
            int kv  = fid & 7;
            int m = m0 + row;
            float4 v = make_float4(0.f, 0.f, 0.f, 0.f);
            if (m < NN) {
                v = *(const float4*)(X + (size_t)m * K_DIM + kc * 32 + kv * 4);
                if (use_bn) {
                    int ch = kc * 32 + kv * 4;
                    v.x = fmaxf(0.f, v.x * g_scale[ch + 0] + g_shift[ch + 0]);
                    v.y = fmaxf(0.f, v.y * g_scale[ch + 1] + g_shift[ch + 1]);
                    v.z = fmaxf(0.f, v.z * g_scale[ch + 2] + g_shift[ch + 2]);
                    v.w = fmaxf(0.f, v.w * g_scale[ch + 3] + g_shift[ch + 3]);
                }
            }
            float* xp = xs + row * XP + kv * 4;
            xp[0] = to_tf32(v.x); xp[1] = to_tf32(v.y);
            xp[2] = to_tf32(v.z); xp[3] = to_tf32(v.w);
        }
        // W chunk: 32 k x BN
#pragma unroll
        for (int i = 0; i < BN / 32; i++) {
            int fid = tid + i * 256;
            int row = fid / (BN / 4);
            int c   = fid % (BN / 4);
            float4 v = *(const float4*)(W + (size_t)(kc * 32 + row) * BN + c * 4);
            float* wp = ws + row * WP + c * 4;
            wp[0] = to_tf32(v.x); wp[1] = to_tf32(v.y);
            wp[2] = to_tf32(v.z); wp[3] = to_tf32(v.w);
        }
        __syncthreads();

#pragma unroll
        for (int ks = 0; ks < 4; ks++) {
            int k0 = ks * 8;
            float a[4][4];
#pragma unroll
            for (int mt = 0; mt < 4; mt++) {
                int rb = (warpM * 64 + mt * 16) * XP;
                a[mt][0] = xs[rb + gid * XP + k0 + tig];
                a[mt][1] = xs[rb + (gid + 8) * XP + k0 + tig];
                a[mt][2] = xs[rb + gid * XP + k0 + tig + 4];
                a[mt][3] = xs[rb + (gid + 8) * XP + k0 + tig + 4];
            }
            float b[NT][2];
#pragma unroll
            for (int nt = 0; nt < NT; nt++) {
                int col = warpN * WN + nt * 8 + gid;
                b[nt][0] = ws[(k0 + tig) * WP + col];
                b[nt][1] = ws[(k0 + tig + 4) * WP + col];
            }
#pragma unroll
            for (int mt = 0; mt < 4; mt++)
#pragma unroll
                for (int nt = 0; nt < NT; nt++)
                    mma_tf32(acc[mt][nt][0], acc[mt][nt][1], acc[mt][nt][2], acc[mt][nt][3],
                             a[mt][0], a[mt][1], a[mt][2], a[mt][3],
                             b[nt][0], b[nt][1]);
        }
        __syncthreads();
    }

    // epilogue: c0,c1 at (gid, tig*2), c2,c3 at (gid+8, tig*2)
#pragma unroll
    for (int mt = 0; mt < 4; mt++) {
        int r0 = m0 + warpM * 64 + mt * 16 + gid;
#pragma unroll
        for (int nt = 0; nt < NT; nt++) {
            int cc = warpN * WN + nt * 8 + tig * 2;
            if (r0 < NN)
                *(float2*)(g_h + (size_t)r0 * BN + cc)
                    = make_float2(acc[mt][nt][0], acc[mt][nt][1]);
            if (r0 + 8 < NN)
                *(float2*)(g_h + (size_t)(r0 + 8) * BN + cc)
                    = make_float2(acc[mt][nt][2], acc[mt][nt][3]);
        }
    }
}

// ---------------- aggregation: out[n] = sum_{e: dst=n} h[src]*norm + h[n]*dinv^2 + bias ----------------
// outp == nullptr -> write to g_a.
template <int D>
__global__ __launch_bounds__(256) void k_agg(
    const float* __restrict__ bias, float* __restrict__ outp)
{
    const int warp = (blockIdx.x * blockDim.x + threadIdx.x) >> 5;
    const int lane = threadIdx.x & 31;
    if (warp >= NN) return;

    const float* H = g_h;
    float* out = outp ? outp : g_a;

    constexpr int VEC = D / 32;   // 4 (D=128) or 2 (D=64)
    float acc[VEC];

    float dn = g_dinv[warp];
    float selfw = dn * dn;
    {
        const float* hp = H + (size_t)warp * D + lane * VEC;
        if (VEC == 4) {
            float4 h4 = *(const float4*)hp;
            acc[0] = h4.x * selfw; acc[1] = h4.y * selfw;
            acc[2] = h4.z * selfw; acc[3] = h4.w * selfw;
        } else {
            float2 h2 = *(const float2*)hp;
            acc[0] = h2.x * selfw; acc[1] = h2.y * selfw;
        }
    }

    int beg = g_rowptr[warp];
    int end = g_rowptr[warp + 1];
    for (int base = beg; base < end; base += 32) {
        int idx = base + lane;
        int c = 0; float v = 0.f;
        if (idx < end) { c = g_col[idx]; v = g_val[idx]; }
        int cnt = min(32, end - base);
        for (int j = 0; j < cnt; j++) {
            int s   = __shfl_sync(0xffffffffu, c, j);
            float w = __shfl_sync(0xffffffffu, v, j);
            const float* hp = H + (size_t)s * D + lane * VEC;
            if (VEC == 4) {
                float4 h4 = *(const float4*)hp;
                acc[0] = fmaf(h4.x, w, acc[0]); acc[1] = fmaf(h4.y, w, acc[1]);
                acc[2] = fmaf(h4.z, w, acc[2]); acc[3] = fmaf(h4.w, w, acc[3]);
            } else {
                float2 h2 = *(const float2*)hp;
                acc[0] = fmaf(h2.x, w, acc[0]); acc[1] = fmaf(h2.y, w, acc[1]);
            }
        }
    }

    float* op = out + (size_t)warp * D + lane * VEC;
    if (VEC == 4) {
        float4 b4 = *(const float4*)(bias + lane * 4);
        *(float4*)op = make_float4(acc[0] + b4.x, acc[1] + b4.y, acc[2] + b4.z, acc[3] + b4.w);
    } else {
        float2 b2 = *(const float2*)(bias + lane * 2);
        *(float2*)op = make_float2(acc[0] + b2.x, acc[1] + b2.y);
    }
}

// ---------------- batch-norm stats (over g_a) ----------------
__global__ void k_zero_stats() {
    int c = threadIdx.x;
    if (c < 128) { g_sum[c] = 0.f; g_ssq[c] = 0.f; }
}

#define STATS_RPB 250
__global__ __launch_bounds__(128) void k_stats() {
    int c = threadIdx.x;
    int r0 = blockIdx.x * STATS_RPB;
    float sum = 0.f, ssq = 0.f;
    int rend = min(r0 + STATS_RPB, NN);
    for (int r = r0; r < rend; r++) {
        float v = g_a[(size_t)r * 128 + c];
        sum += v; ssq += v * v;
    }
    atomicAdd(&g_sum[c], sum);
    atomicAdd(&g_ssq[c], ssq);
}

__global__ void k_bnfin(const float* __restrict__ gamma, const float* __restrict__ beta) {
    int c = threadIdx.x;
    if (c < 128) {
        float mean = g_sum[c] / (float)NN;
        float var  = g_ssq[c] / (float)NN - mean * mean;
        float inv  = rsqrtf(var + BN_EPS);
        float sc   = gamma[c] * inv;
        g_scale[c] = sc;
        g_shift[c] = beta[c] - mean * sc;
    }
}

// ---------------- launch (pure kernel launches; no runtime API) ----------------
extern "C" void kernel_launch(void* const* d_in, const int* in_sizes, int n_in,
                              void* d_out, int out_size) {
    const float* x   = (const float*)d_in[0];
    const void*  ei  = d_in[1];                   // int32 or int64, detected on device
    const float* ew  = (const float*)d_in[2];
    const float* W1  = (const float*)d_in[3];
    const float* b1  = (const float*)d_in[4];
    const float* W2  = (const float*)d_in[5];
    const float* b2  = (const float*)d_in[6];
    const float* W3  = (const float*)d_in[7];
    const float* b3  = (const float*)d_in[8];
    const float* g1  = (const float*)d_in[9];
    const float* be1 = (const float*)d_in[10];
    const float* g2  = (const float*)d_in[11];
    const float* be2 = (const float*)d_in[12];
    float* out = (float*)d_out;

    const int nb_n = (NN + 255) / 256;
    const int nb_e = (EE + 255) / 256;
    const int gemm_blocks = (NN + 127) / 128;
    const int agg_blocks = (NN + 7) / 8;          // 8 warps/block
    const int stats_blocks = (NN + STATS_RPB - 1) / STATS_RPB;

    // --- graph preprocessing ---
    k_detect<<<1, 1>>>((const int*)ei);
    k_init<<<nb_n, 256>>>();
    k_degcount<<<nb_e, 256>>>(ei, ew);
    k_dinv<<<nb_n, 256>>>();
    k_scan<<<1, 1024>>>();
    k_fill<<<nb_e, 256>>>(ei, ew);

    // --- layer 1 ---
    k_gemm_tc<128><<<gemm_blocks, 256>>>(x, W1, 0);
    k_agg<128><<<agg_blocks, 256>>>(b1, nullptr);
    k_zero_stats<<<1, 128>>>();
    k_stats<<<stats_blocks, 128>>>();
    k_bnfin<<<1, 128>>>(g1, be1);

    // --- layer 2 (BN1+ReLU fused into GEMM X-load) ---
    k_gemm_tc<128><<<gemm_blocks, 256>>>(nullptr, W2, 1);
    k_agg<128><<<agg_blocks, 256>>>(b2, nullptr);
    k_zero_stats<<<1, 128>>>();
    k_stats<<<stats_blocks, 128>>>();
    k_bnfin<<<1, 128>>>(g2, be2);

    // --- layer 3 (BN2+ReLU fused; 64-wide output straight to d_out) ---
    k_gemm_tc<64><<<gemm_blocks, 256>>>(nullptr, W3, 1);
    k_agg<64><<<agg_blocks, 256>>>(b3, out);
}